// round 2
// baseline (speedup 1.0000x reference)
#include <cuda_runtime.h>
#include <cstdint>

// ---------------------------------------------------------------------------
// GroupedLinear: out[t, o] = sum_i X[t, i] * W[g(t), o, i]
// G=8 balanced groups, 2048 tokens/group, in=out=2048, fp32.
//
// Baseline-PTX tensor-core GEMM (the harness ptxas targets plain sm_103 — no
// 'a'-suffix features, so no tcgen05/TMEM): cp.async + ldmatrix +
// mma.sync.m16n8k8.tf32 with inline cvt.rna.tf32 rounding (unbiased tf32).
// ---------------------------------------------------------------------------

#define NUM_GROUPS 8
#define IN_F       2048
#define OUT_F      2048
#define TOKENS     16384

constexpr int BM = 128;
constexpr int BN = 128;
constexpr int BK = 32;                       // 32 fp32 = 128 B rows
constexpr int THREADS = 256;                 // 8 warps: 2 (M) x 4 (N)
constexpr int STAGES = 3;
constexpr int KITERS = IN_F / BK;            // 64
constexpr int A_BYTES = BM * BK * 4;         // 16 KB
constexpr int B_BYTES = BN * BK * 4;         // 16 KB
constexpr int STAGE_BYTES = A_BYTES + B_BYTES;   // 32 KB
constexpr int SMEM_TOTAL = STAGES * STAGE_BYTES; // 96 KB

// ---------------------------------------------------------------------------
// PTX helpers (all baseline PTX, sm_80-level)
// ---------------------------------------------------------------------------
__device__ __forceinline__ uint32_t smem_u32(const void* p) {
    uint32_t a;
    asm("{ .reg .u64 t; cvta.to.shared.u64 t, %1; cvt.u32.u64 %0, t; }"
        : "=r"(a) : "l"(p));
    return a;
}

// SW128 swizzle: XOR row bits [9:7] into 16B-chunk bits [6:4]
__device__ __forceinline__ uint32_t swz(uint32_t o) {
    return o ^ ((o >> 3) & 0x70);
}

__device__ __forceinline__ void cp16(uint32_t dst, const void* src) {
    asm volatile("cp.async.cg.shared.global [%0], [%1], 16;"
                 :: "r"(dst), "l"(src));
}
__device__ __forceinline__ void cp_commit() {
    asm volatile("cp.async.commit_group;");
}
template <int N>
__device__ __forceinline__ void cp_wait() {
    asm volatile("cp.async.wait_group %0;" :: "n"(N));
}

__device__ __forceinline__ void ldsm4(uint32_t* r, uint32_t addr) {
    asm volatile("ldmatrix.sync.aligned.m8n8.x4.shared.b16 {%0,%1,%2,%3}, [%4];"
                 : "=r"(r[0]), "=r"(r[1]), "=r"(r[2]), "=r"(r[3]) : "r"(addr));
}

// fp32 -> tf32 with round-to-nearest (removes HW truncation bias)
__device__ __forceinline__ uint32_t to_tf32(uint32_t x) {
    uint32_t r;
    asm("cvt.rna.tf32.f32 %0, %1;" : "=r"(r) : "f"(__uint_as_float(x)));
    return r;
}

__device__ __forceinline__ void mma_tf32(float* c, const uint32_t* a,
                                         uint32_t b0, uint32_t b1) {
    asm volatile(
        "mma.sync.aligned.m16n8k8.row.col.f32.tf32.tf32.f32 "
        "{%0,%1,%2,%3}, {%4,%5,%6,%7}, {%8,%9}, {%0,%1,%2,%3};"
        : "+f"(c[0]), "+f"(c[1]), "+f"(c[2]), "+f"(c[3])
        : "r"(a[0]), "r"(a[1]), "r"(a[2]), "r"(a[3]), "r"(b0), "r"(b1));
}

// ---------------------------------------------------------------------------
// Stage loader: 4 A-chunks + 4 B-chunks (16 B each) per thread
// ---------------------------------------------------------------------------
__device__ __forceinline__ void load_stage(uint32_t sb, int stage,
                                           const float* __restrict__ Ag,
                                           const float* __restrict__ Bg,
                                           int k0, int tid) {
    const uint32_t sA = sb + stage * STAGE_BYTES;
    const uint32_t sB = sA + A_BYTES;
    #pragma unroll
    for (int i = 0; i < 4; ++i) {
        const int c   = tid + THREADS * i;       // 0..1023
        const int row = c >> 3;                  // 0..127
        const int cc  = c & 7;                   // 16B chunk within row
        const uint32_t d = swz((uint32_t)(row * 128 + cc * 16));
        cp16(sA + d, Ag + (size_t)row * IN_F + k0 + cc * 4);
        cp16(sB + d, Bg + (size_t)row * IN_F + k0 + cc * 4);
    }
}

// ---------------------------------------------------------------------------
// Kernel: one 128x128 output tile per CTA. Warp tile 64(M) x 32(N).
// ---------------------------------------------------------------------------
__global__ void __launch_bounds__(THREADS, 2)
grouped_gemm_tf32(const float* __restrict__ X, const float* __restrict__ W,
                  float* __restrict__ out) {
    extern __shared__ __align__(128) char smem[];
    const uint32_t sb = smem_u32(smem);
    const int tid  = threadIdx.x;
    const int lane = tid & 31;
    const int wid  = tid >> 5;
    const int warp_m = wid & 1;    // 0..1 -> 64-row halves
    const int warp_n = wid >> 1;   // 0..3 -> 32-col quarters

    // Tile mapping: groups outermost (L2 weight reuse), then 16x16 tiles.
    const int b  = blockIdx.x;
    const int g  = b >> 8;
    const int t  = b & 255;
    const int mt = t >> 4;
    const int nt = t & 15;

    const float* Ag = X + (size_t)(g * (TOKENS / NUM_GROUPS) + mt * BM) * IN_F;
    const float* Bg = W + (size_t)(g * OUT_F + nt * BN) * IN_F;

    float acc[4][4][4];
    #pragma unroll
    for (int i = 0; i < 4; ++i)
        #pragma unroll
        for (int j = 0; j < 4; ++j)
            #pragma unroll
            for (int r = 0; r < 4; ++r) acc[i][j][r] = 0.0f;

    // Prologue: fill first STAGES-1 stages
    load_stage(sb, 0, Ag, Bg, 0, tid);
    cp_commit();
    load_stage(sb, 1, Ag, Bg, BK, tid);
    cp_commit();

    for (int kit = 0; kit < KITERS; ++kit) {
        if (kit < KITERS - 1) cp_wait<1>(); else cp_wait<0>();
        __syncthreads();

        if (kit + 2 < KITERS) {
            load_stage(sb, (kit + 2) % STAGES, Ag, Bg, (kit + 2) * BK, tid);
            cp_commit();
        }

        const uint32_t sA = sb + (kit % STAGES) * STAGE_BYTES;
        const uint32_t sB = sA + A_BYTES;

        #pragma unroll
        for (int ks = 0; ks < 4; ++ks) {          // 4 x k8 steps per BK=32
            const int kb = ks * 32;                // byte offset of k8 slice

            // A fragments: 4 m16k8 tiles via ldmatrix.x4 each.
            // lanes 0-7: oct0/kc0, 8-15: oct1/kc0, 16-23: oct0/kc1, 24-31: oct1/kc1
            uint32_t a[4][4];
            #pragma unroll
            for (int i = 0; i < 4; ++i) {
                const uint32_t off = (uint32_t)(
                    (warp_m * 64 + i * 16 + (lane & 15)) * 128 + kb + (lane & 16));
                ldsm4(a[i], sA + swz(off));
                #pragma unroll
                for (int r = 0; r < 4; ++r) a[i][r] = to_tf32(a[i][r]);
            }

            // B fragments: 4 n8k8 tiles; two ldmatrix.x4 (kc0 then kc1).
            // lane -> n-row (warp_n*32 + lane), matrix j = n-octet j.
            uint32_t b0[4], b1[4];
            {
                const uint32_t off0 = (uint32_t)((warp_n * 32 + lane) * 128 + kb);
                ldsm4(b0, sB + swz(off0));
                ldsm4(b1, sB + swz(off0 + 16));
                #pragma unroll
                for (int j = 0; j < 4; ++j) {
                    b0[j] = to_tf32(b0[j]);
                    b1[j] = to_tf32(b1[j]);
                }
            }

            #pragma unroll
            for (int i = 0; i < 4; ++i)
                #pragma unroll
                for (int j = 0; j < 4; ++j)
                    mma_tf32(acc[i][j], a[i], b0[j], b1[j]);
        }
    }

    // Epilogue: C frag (m16n8): thread holds (r=t/4, c=2*(t%4)) pairs at rows r, r+8
    const int m0 = g * (TOKENS / NUM_GROUPS) + mt * BM + warp_m * 64;
    const int n0 = nt * BN + warp_n * 32;
    #pragma unroll
    for (int i = 0; i < 4; ++i) {
        const int r = m0 + i * 16 + (lane >> 2);
        float* p0 = out + (size_t)r * OUT_F + n0 + 2 * (lane & 3);
        float* p1 = p0 + (size_t)8 * OUT_F;
        #pragma unroll
        for (int j = 0; j < 4; ++j) {
            *reinterpret_cast<float2*>(p0 + j * 8) =
                make_float2(acc[i][j][0], acc[i][j][1]);
            *reinterpret_cast<float2*>(p1 + j * 8) =
                make_float2(acc[i][j][2], acc[i][j][3]);
        }
    }
}

// ---------------------------------------------------------------------------
// Host launch
// ---------------------------------------------------------------------------
extern "C" void kernel_launch(void* const* d_in, const int* in_sizes, int n_in,
                              void* d_out, int out_size) {
    const float* x = (const float*)d_in[0];   // [16384, 2048]
    const float* w = (const float*)d_in[1];   // [8, 2048, 2048]
    float* out = (float*)d_out;               // [16384, 2048]

    static bool attr_set = false;
    if (!attr_set) {
        cudaFuncSetAttribute(grouped_gemm_tf32,
                             cudaFuncAttributeMaxDynamicSharedMemorySize,
                             SMEM_TOTAL);
        attr_set = true;
    }

    const int grid = NUM_GROUPS * (TOKENS / NUM_GROUPS / BM) * (OUT_F / BN); // 2048
    grouped_gemm_tf32<<<grid, THREADS, SMEM_TOTAL>>>(x, w, out);
}

// round 3
// speedup vs baseline: 1.0572x; 1.0572x over previous
#include <cuda_runtime.h>
#include <cstdint>

// ---------------------------------------------------------------------------
// GroupedLinear: out[t, o] = sum_i X[t, i] * W[g(t), o, i]
// G=8 balanced groups, 2048 tokens/group, in=out=2048, fp32.
//
// R2 analysis: issue-bound, not memory-bound (dram 5.6%). Inline cvt.rna.tf32
// was ~45% of non-MMA issue slots. This round: pre-round X and W into scratch
// (DRAM is idle), making the GEMM mainloop pure HMMA+LDSM.
// ---------------------------------------------------------------------------

#define NUM_GROUPS 8
#define IN_F       2048
#define OUT_F      2048
#define TOKENS     16384

// Pre-rounded tf32 copies (device-global scratch: allowed)
__device__ float g_xr[(size_t)TOKENS * IN_F];                 // 128 MB
__device__ float g_wr[(size_t)NUM_GROUPS * OUT_F * IN_F];     // 128 MB

constexpr int BM = 128;
constexpr int BN = 128;
constexpr int BK = 32;                       // 32 fp32 = 128 B rows
constexpr int THREADS = 256;                 // 8 warps: 2 (M) x 4 (N)
constexpr int STAGES = 3;
constexpr int KITERS = IN_F / BK;            // 64
constexpr int A_BYTES = BM * BK * 4;         // 16 KB
constexpr int B_BYTES = BN * BK * 4;         // 16 KB
constexpr int STAGE_BYTES = A_BYTES + B_BYTES;   // 32 KB
constexpr int SMEM_TOTAL = STAGES * STAGE_BYTES; // 96 KB

// ---------------------------------------------------------------------------
// PTX helpers (baseline PTX only — harness ptxas targets plain sm_103)
// ---------------------------------------------------------------------------
__device__ __forceinline__ uint32_t smem_u32(const void* p) {
    uint32_t a;
    asm("{ .reg .u64 t; cvta.to.shared.u64 t, %1; cvt.u32.u64 %0, t; }"
        : "=r"(a) : "l"(p));
    return a;
}

// SW128 swizzle: XOR row bits [9:7] into 16B-chunk bits [6:4]
__device__ __forceinline__ uint32_t swz(uint32_t o) {
    return o ^ ((o >> 3) & 0x70);
}

__device__ __forceinline__ void cp16(uint32_t dst, const void* src) {
    asm volatile("cp.async.cg.shared.global [%0], [%1], 16;"
                 :: "r"(dst), "l"(src));
}
__device__ __forceinline__ void cp_commit() {
    asm volatile("cp.async.commit_group;");
}
template <int N>
__device__ __forceinline__ void cp_wait() {
    asm volatile("cp.async.wait_group %0;" :: "n"(N));
}

__device__ __forceinline__ void ldsm4(uint32_t* r, uint32_t addr) {
    asm volatile("ldmatrix.sync.aligned.m8n8.x4.shared.b16 {%0,%1,%2,%3}, [%4];"
                 : "=r"(r[0]), "=r"(r[1]), "=r"(r[2]), "=r"(r[3]) : "r"(addr));
}

__device__ __forceinline__ void mma_tf32(float* c, const uint32_t* a,
                                         uint32_t b0, uint32_t b1) {
    asm volatile(
        "mma.sync.aligned.m16n8k8.row.col.f32.tf32.tf32.f32 "
        "{%0,%1,%2,%3}, {%4,%5,%6,%7}, {%8,%9}, {%0,%1,%2,%3};"
        : "+f"(c[0]), "+f"(c[1]), "+f"(c[2]), "+f"(c[3])
        : "r"(a[0]), "r"(a[1]), "r"(a[2]), "r"(a[3]), "r"(b0), "r"(b1));
}

// ---------------------------------------------------------------------------
// Pre-pass: fp32 -> round-to-nearest tf32 copy (removes HW truncation bias
// without any mainloop cvt instructions)
// ---------------------------------------------------------------------------
__global__ void __launch_bounds__(256) round_tf32_kernel(
    const float4* __restrict__ in, float4* __restrict__ out, int n4) {
    int i = blockIdx.x * blockDim.x + threadIdx.x;
    if (i >= n4) return;
    float4 v = in[i];
    uint4 o;
    asm("cvt.rna.tf32.f32 %0, %1;" : "=r"(o.x) : "f"(v.x));
    asm("cvt.rna.tf32.f32 %0, %1;" : "=r"(o.y) : "f"(v.y));
    asm("cvt.rna.tf32.f32 %0, %1;" : "=r"(o.z) : "f"(v.z));
    asm("cvt.rna.tf32.f32 %0, %1;" : "=r"(o.w) : "f"(v.w));
    reinterpret_cast<uint4*>(out)[i] = o;
}

// ---------------------------------------------------------------------------
// Stage loader: 4 A-chunks + 4 B-chunks (16 B each) per thread
// ---------------------------------------------------------------------------
__device__ __forceinline__ void load_stage(uint32_t sb, int stage,
                                           const float* __restrict__ Ag,
                                           const float* __restrict__ Bg,
                                           int k0, int tid) {
    const uint32_t sA = sb + stage * STAGE_BYTES;
    const uint32_t sB = sA + A_BYTES;
    #pragma unroll
    for (int i = 0; i < 4; ++i) {
        const int c   = tid + THREADS * i;       // 0..1023
        const int row = c >> 3;                  // 0..127
        const int cc  = c & 7;                   // 16B chunk within row
        const uint32_t d = swz((uint32_t)(row * 128 + cc * 16));
        cp16(sA + d, Ag + (size_t)row * IN_F + k0 + cc * 4);
        cp16(sB + d, Bg + (size_t)row * IN_F + k0 + cc * 4);
    }
}

// ---------------------------------------------------------------------------
// Kernel: one 128x128 output tile per CTA. Warp tile 64(M) x 32(N).
// Mainloop per k8: 16 HMMA + 6 LDSM, zero cvt.
// ---------------------------------------------------------------------------
__global__ void __launch_bounds__(THREADS, 2)
grouped_gemm_tf32(const float* __restrict__ X, const float* __restrict__ W,
                  float* __restrict__ out) {
    extern __shared__ __align__(1024) char smem[];
    const uint32_t sb = smem_u32(smem);
    const int tid  = threadIdx.x;
    const int lane = tid & 31;
    const int wid  = tid >> 5;
    const int warp_m = wid & 1;    // 0..1 -> 64-row halves
    const int warp_n = wid >> 1;   // 0..3 -> 32-col quarters

    // Tile mapping: groups outermost (L2 weight reuse), then 16x16 tiles.
    const int b  = blockIdx.x;
    const int g  = b >> 8;
    const int t  = b & 255;
    const int mt = t >> 4;
    const int nt = t & 15;

    const float* Ag = X + (size_t)(g * (TOKENS / NUM_GROUPS) + mt * BM) * IN_F;
    const float* Bg = W + (size_t)(g * OUT_F + nt * BN) * IN_F;

    float acc[4][4][4];
    #pragma unroll
    for (int i = 0; i < 4; ++i)
        #pragma unroll
        for (int j = 0; j < 4; ++j)
            #pragma unroll
            for (int r = 0; r < 4; ++r) acc[i][j][r] = 0.0f;

    // Per-warp ldmatrix base offsets within a stage (k8 slice ks reached by
    // XOR with ks*32: the k-offset bits [5:6] are disjoint from the base's
    // low bits, and the SW128 mask only covers bits [4:6]).
    uint32_t a_off[4];
    #pragma unroll
    for (int i = 0; i < 4; ++i)
        a_off[i] = swz((uint32_t)(
            (warp_m * 64 + i * 16 + (lane & 15)) * 128 + (lane & 16)));
    const uint32_t b_off0 = swz((uint32_t)((warp_n * 32 + lane) * 128));
    const uint32_t b_off1 = swz((uint32_t)((warp_n * 32 + lane) * 128 + 16));

    // Prologue: fill first STAGES-1 stages
    load_stage(sb, 0, Ag, Bg, 0, tid);
    cp_commit();
    load_stage(sb, 1, Ag, Bg, BK, tid);
    cp_commit();

    for (int kit = 0; kit < KITERS; ++kit) {
        if (kit < KITERS - 1) cp_wait<1>(); else cp_wait<0>();
        __syncthreads();

        if (kit + 2 < KITERS) {
            load_stage(sb, (kit + 2) % STAGES, Ag, Bg, (kit + 2) * BK, tid);
            cp_commit();
        }

        const uint32_t sA = sb + (kit % STAGES) * STAGE_BYTES;
        const uint32_t sB = sA + A_BYTES;

        #pragma unroll
        for (int ks = 0; ks < 4; ++ks) {          // 4 x k8 steps per BK=32
            const uint32_t kx = (uint32_t)(ks * 32);  // XOR-applied k8 offset

            uint32_t a[4][4];
            #pragma unroll
            for (int i = 0; i < 4; ++i)
                ldsm4(a[i], sA + (a_off[i] ^ kx));

            uint32_t b0[4], b1[4];
            ldsm4(b0, sB + (b_off0 ^ kx));
            ldsm4(b1, sB + (b_off1 ^ kx));

            #pragma unroll
            for (int i = 0; i < 4; ++i)
                #pragma unroll
                for (int j = 0; j < 4; ++j)
                    mma_tf32(acc[i][j], a[i], b0[j], b1[j]);
        }
    }

    // Epilogue: m16n8 C frag: thread holds (r=t/4, c=2*(t%4)) pairs at rows r, r+8
    const int m0 = g * (TOKENS / NUM_GROUPS) + mt * BM + warp_m * 64;
    const int n0 = nt * BN + warp_n * 32;
    #pragma unroll
    for (int i = 0; i < 4; ++i) {
        const int r = m0 + i * 16 + (lane >> 2);
        float* p0 = out + (size_t)r * OUT_F + n0 + 2 * (lane & 3);
        float* p1 = p0 + (size_t)8 * OUT_F;
        #pragma unroll
        for (int j = 0; j < 4; ++j) {
            *reinterpret_cast<float2*>(p0 + j * 8) =
                make_float2(acc[i][j][0], acc[i][j][1]);
            *reinterpret_cast<float2*>(p1 + j * 8) =
                make_float2(acc[i][j][2], acc[i][j][3]);
        }
    }
}

// ---------------------------------------------------------------------------
// Host launch
// ---------------------------------------------------------------------------
extern "C" void kernel_launch(void* const* d_in, const int* in_sizes, int n_in,
                              void* d_out, int out_size) {
    const float* x = (const float*)d_in[0];   // [16384, 2048]
    const float* w = (const float*)d_in[1];   // [8, 2048, 2048]
    float* out = (float*)d_out;               // [16384, 2048]

    float* xr = nullptr;
    float* wr = nullptr;
    cudaGetSymbolAddress((void**)&xr, g_xr);
    cudaGetSymbolAddress((void**)&wr, g_wr);

    static bool attr_set = false;
    if (!attr_set) {
        cudaFuncSetAttribute(grouped_gemm_tf32,
                             cudaFuncAttributeMaxDynamicSharedMemorySize,
                             SMEM_TOTAL);
        attr_set = true;
    }

    // Pre-pass: round-to-nearest tf32 copies (X and W)
    const int n4 = (TOKENS * IN_F) / 4;       // 8,388,608 float4 per tensor
    round_tf32_kernel<<<(n4 + 255) / 256, 256>>>((const float4*)x, (float4*)xr, n4);
    round_tf32_kernel<<<(n4 + 255) / 256, 256>>>((const float4*)w, (float4*)wr, n4);

    const int grid = NUM_GROUPS * (TOKENS / NUM_GROUPS / BM) * (OUT_F / BN); // 2048
    grouped_gemm_tf32<<<grid, THREADS, SMEM_TOTAL>>>(xr, wr, out);
}